// round 15
// baseline (speedup 1.0000x reference)
#include <cuda_runtime.h>
#include <cuda_fp16.h>
#include <cstdint>
#include <cstddef>

// Problem dims
#define BATCH 2
#define TSEQ  2048
#define EDIM  1024
#define FDIM  4096
#define NHEAD 16
#define HDIM  64
#define MTOK  (BATCH*TSEQ)   // 4096 rows
#define QKVN  (3*EDIM)       // 3072

// ---------------- scratch (device globals: allocation-free) ----------------
__device__ float  g_x1  [MTOK*EDIM];
__device__ __half g_ah  [MTOK*EDIM];     // ln outputs / attention output
__device__ __half g_bh  [MTOK*FDIM];     // mlp hidden
__device__ __half g_qkvh[MTOK*QKVN];     // fused QKV
__device__ __half g_wqkv[EDIM*QKVN];     // [1024 k][3072 n] = [Wq|Wk|Wv] row-major
__device__ __half g_woh [EDIM*EDIM];     // [K][N] row-major fp16
__device__ __half g_w1h [EDIM*FDIM];
__device__ __half g_w2h [FDIM*EDIM];

// ---------------- PTX helpers (sm_80-compatible only) ----------------
__device__ __forceinline__ uint32_t smem_u32(const void* p) {
    uint32_t a;
    asm("{ .reg .u64 t; cvta.to.shared.u64 t, %1; cvt.u32.u64 %0, t; }" : "=r"(a) : "l"(p));
    return a;
}
#define SWZ128(o) ((o) ^ ((((uint32_t)(o)) >> 3) & 0x70u))

#define CP_ASYNC16(dst, src) \
    asm volatile("cp.async.cg.shared.global [%0], [%1], 16;" :: "r"(dst), "l"(src) : "memory")
#define CP_COMMIT()  asm volatile("cp.async.commit_group;" ::: "memory")
#define CP_WAIT(n)   asm volatile("cp.async.wait_group %0;" :: "n"(n) : "memory")

__device__ __forceinline__ void ldsm_x4(uint32_t* r, uint32_t addr) {
    asm volatile("ldmatrix.sync.aligned.m8n8.x4.shared.b16 {%0,%1,%2,%3}, [%4];"
                 : "=r"(r[0]), "=r"(r[1]), "=r"(r[2]), "=r"(r[3]) : "r"(addr));
}
__device__ __forceinline__ void ldsm_x4t(uint32_t* r, uint32_t addr) {
    asm volatile("ldmatrix.sync.aligned.m8n8.x4.trans.shared.b16 {%0,%1,%2,%3}, [%4];"
                 : "=r"(r[0]), "=r"(r[1]), "=r"(r[2]), "=r"(r[3]) : "r"(addr));
}
__device__ __forceinline__ void mma16816(float* c, const uint32_t* a, const uint32_t* b) {
    asm volatile("mma.sync.aligned.m16n8k16.row.col.f32.f16.f16.f32 "
                 "{%0,%1,%2,%3}, {%4,%5,%6,%7}, {%8,%9}, {%0,%1,%2,%3};"
                 : "+f"(c[0]), "+f"(c[1]), "+f"(c[2]), "+f"(c[3])
                 : "r"(a[0]), "r"(a[1]), "r"(a[2]), "r"(a[3]),
                   "r"(b[0]), "r"(b[1]));
}
__device__ __forceinline__ uint32_t packh2(float a, float b) {
    __half2 t = __floats2half2_rn(a, b);
    return *(uint32_t*)&t;
}
__device__ __forceinline__ float ex2(float x) {
    float r;
    asm("ex2.approx.f32 %0, %1;" : "=f"(r) : "f"(x));
    return r;
}

// ---------------- LayerNorm -> fp16, warp-per-row (no barriers) ---------------
__global__ __launch_bounds__(256)
void ln_kernel(const float* __restrict__ x, const float* __restrict__ g,
               const float* __restrict__ b, __half* __restrict__ yh)
{
    int wid = threadIdx.x >> 5, lane = threadIdx.x & 31;
    int row = blockIdx.x * 8 + wid;
    const float* xr = x + (size_t)row * EDIM;
    float v[32];
    float s = 0.f;
    #pragma unroll
    for (int i = 0; i < 8; i++) {
        float4 t = *(const float4*)(xr + i * 128 + lane * 4);
        v[i*4+0] = t.x; v[i*4+1] = t.y; v[i*4+2] = t.z; v[i*4+3] = t.w;
        s += t.x + t.y + t.z + t.w;
    }
    #pragma unroll
    for (int o = 16; o > 0; o >>= 1) s += __shfl_xor_sync(0xffffffffu, s, o);
    float mean = s * (1.0f / EDIM);
    float s2 = 0.f;
    #pragma unroll
    for (int i = 0; i < 32; i++) { float d = v[i] - mean; s2 += d * d; }
    #pragma unroll
    for (int o = 16; o > 0; o >>= 1) s2 += __shfl_xor_sync(0xffffffffu, s2, o);
    float r = rsqrtf(s2 * (1.0f / EDIM) + 1e-5f);
    __half* yr = yh + (size_t)row * EDIM;
    #pragma unroll
    for (int i = 0; i < 8; i++) {
        int col = i * 128 + lane * 4;
        float4 g4 = *(const float4*)(g + col);
        float4 b4 = *(const float4*)(b + col);
        float o0 = (v[i*4+0] - mean) * r * g4.x + b4.x;
        float o1 = (v[i*4+1] - mean) * r * g4.y + b4.y;
        float o2 = (v[i*4+2] - mean) * r * g4.z + b4.z;
        float o3 = (v[i*4+3] - mean) * r * g4.w + b4.w;
        *(__half2*)(yr + col)     = __floats2half2_rn(o0, o1);
        *(__half2*)(yr + col + 2) = __floats2half2_rn(o2, o3);
    }
}

// ---------------- weight convert (fp32 -> fp16, row-major, no transpose) -----
// Wq/Wk/Wv are column-concatenated into wqkv[k][3072]. Pure streaming.
__global__ __launch_bounds__(256)
void wconv_all(const float* __restrict__ Wq, const float* __restrict__ Wk,
               const float* __restrict__ Wv, const float* __restrict__ Wo,
               const float* __restrict__ W1, const float* __restrict__ W2,
               __half* __restrict__ wqkv, __half* __restrict__ woh,
               __half* __restrict__ w1h, __half* __restrict__ w2h)
{
    int bid = blockIdx.x;
    const float* W; __half* T;
    size_t e, dstoff;
    if (bid < 2048) {                      // Wq,Wk,Wv,Wo: 512 CTAs each
        int seg = bid >> 9, loc = bid & 511;
        e = ((size_t)loc * 256 + threadIdx.x) * 8;
        if (seg < 3) {
            W = (seg == 0) ? Wq : (seg == 1) ? Wk : Wv;
            T = wqkv;
            size_t k = e >> 10, n = e & 1023;
            dstoff = k * QKVN + (size_t)seg * 1024 + n;
        } else {
            W = Wo; T = woh; dstoff = e;
        }
    } else if (bid < 4096) {               // W1: 2048 CTAs
        int loc = bid - 2048;
        e = ((size_t)loc * 256 + threadIdx.x) * 8;
        W = W1; T = w1h; dstoff = e;
    } else {                               // W2: 2048 CTAs
        int loc = bid - 4096;
        e = ((size_t)loc * 256 + threadIdx.x) * 8;
        W = W2; T = w2h; dstoff = e;
    }
    float4 a = *(const float4*)(W + e);
    float4 c = *(const float4*)(W + e + 4);
    __half2 h0 = __floats2half2_rn(a.x, a.y);
    __half2 h1 = __floats2half2_rn(a.z, a.w);
    __half2 h2 = __floats2half2_rn(c.x, c.y);
    __half2 h3 = __floats2half2_rn(c.z, c.w);
    uint2 p0 = make_uint2(*(uint32_t*)&h0, *(uint32_t*)&h1);
    uint2 p1 = make_uint2(*(uint32_t*)&h2, *(uint32_t*)&h3);
    *(uint2*)(T + dstoff)     = p0;
    *(uint2*)(T + dstoff + 4) = p1;
}

// ---------------- mma.sync fp16 GEMM (row-major B, x4t frags, 2 CTAs/SM) -----
// C[M,N] = A[M,K] @ B[K,N] with B row-major fp16. B fragments via
// ldmatrix.x4.trans (same lane pattern as the validated attention V path).
// B stage = two 8KB SW128 subtiles (n 0-63, 64-127 of the CTA's 128 cols).
#define G_TILE_B 16384
#define G_STAGE_B (2*G_TILE_B)
#define G_SMEM (3*G_STAGE_B)     // 96 KB

__global__ __launch_bounds__(256, 2)
void gemm_mma(const __half* __restrict__ Ah, const __half* __restrict__ Bh,
              float* __restrict__ C, __half* __restrict__ Oh,
              const float* __restrict__ bias,
              const float* __restrict__ resid, int relu, int N, int K)
{
    extern __shared__ __align__(1024) char smem[];
    const uint32_t sb = smem_u32(smem);
    const int tid  = threadIdx.x;
    const int wid  = tid >> 5, lane = tid & 31;
    const int wm   = wid >> 2;
    const int wn   = wid & 3;
    const int bm = blockIdx.y, bn = blockIdx.x;

    const size_t arow0 = (size_t)bm * 128;
    const int    bcol0 = bn * 128;

    auto load_stage = [&](int s, int k0) {
        uint32_t base = sb + s * G_STAGE_B;
        #pragma unroll
        for (int it = 0; it < 8; it++) {
            int c = tid + it * 256;
            if (c < 1024) {                 // A: 128 rows x 8 c16
                int r = c >> 3, c16 = c & 7;
                uint32_t dst = base + SWZ128(r * 128 + c16 * 16);
                CP_ASYNC16(dst, Ah + (arow0 + r) * K + k0 + c16 * 8);
            } else {                        // B: 64 k-rows x 16 c16 (256B/row)
                int idx = c & 1023;
                int r = idx >> 4, c16 = idx & 15;
                uint32_t dst = base + G_TILE_B + (c16 >> 3) * 8192
                             + SWZ128(r * 128 + (c16 & 7) * 16);
                CP_ASYNC16(dst, Bh + (size_t)(k0 + r) * N + bcol0 + c16 * 8);
            }
        }
        CP_COMMIT();
    };

    float acc[4][4][4];
    #pragma unroll
    for (int mf = 0; mf < 4; mf++)
        #pragma unroll
        for (int nf = 0; nf < 4; nf++)
            #pragma unroll
            for (int e = 0; e < 4; e++) acc[mf][nf][e] = 0.f;

    const int nch = K >> 6;
    load_stage(0, 0);
    load_stage(1, 64);

    const int a_r  = (lane & 7) + ((lane >> 3) & 1) * 8;
    const int a_cb = (lane >> 4) * 16;
    const int b4_r = lane & 15;              // k row within 16
    const int b4_c = (lane >> 4) * 16;       // byte col within 32
    const uint32_t bsub = (wn >> 1) * 8192;  // n-half subtile
    const int bcolb = (wn & 1) * 64;         // byte col base within subtile

    int s3 = 0;
    for (int i = 0; i < nch; i++) {
        if (i + 1 < nch) { CP_WAIT(1); } else { CP_WAIT(0); }
        __syncthreads();
        if (i + 2 < nch) {
            int sn = s3 + 2; if (sn >= 3) sn -= 3;
            load_stage(sn, (i + 2) << 6);
        }

        uint32_t tA = sb + s3 * G_STAGE_B;
        uint32_t tB = tA + G_TILE_B + bsub;

        #pragma unroll
        for (int ks = 0; ks < 4; ks++) {
            uint32_t ra[4][4], rb[2][4];
            #pragma unroll
            for (int mf = 0; mf < 4; mf++) {
                uint32_t off = SWZ128((wm * 64 + mf * 16 + a_r) * 128 + ks * 32 + a_cb);
                ldsm_x4(ra[mf], tA + off);
            }
            #pragma unroll
            for (int np = 0; np < 2; np++) {
                uint32_t off = SWZ128((ks * 16 + b4_r) * 128 + bcolb + np * 32 + b4_c);
                ldsm_x4t(rb[np], tB + off);
            }
            #pragma unroll
            for (int mf = 0; mf < 4; mf++)
                #pragma unroll
                for (int np = 0; np < 2; np++) {
                    mma16816(acc[mf][2 * np],     ra[mf], rb[np]);
                    mma16816(acc[mf][2 * np + 1], ra[mf], rb[np] + 2);
                }
        }
        if (++s3 == 3) s3 = 0;
    }

    int rbase = bm * 128 + wm * 64 + (lane >> 2);
    int cbase = bn * 128 + wn * 32 + (lane & 3) * 2;
    #pragma unroll
    for (int mf = 0; mf < 4; mf++) {
        #pragma unroll
        for (int half = 0; half < 2; half++) {
            int row = rbase + mf * 16 + half * 8;
            #pragma unroll
            for (int nf = 0; nf < 4; nf++) {
                int col = cbase + nf * 8;
                float ox = acc[mf][nf][half * 2 + 0];
                float oy = acc[mf][nf][half * 2 + 1];
                if (bias) {
                    float2 bb = *(const float2*)(bias + col);
                    ox += bb.x; oy += bb.y;
                }
                if (relu) { ox = fmaxf(ox, 0.f); oy = fmaxf(oy, 0.f); }
                if (resid) {
                    float2 rr = *(const float2*)(resid + (size_t)row * N + col);
                    ox += rr.x; oy += rr.y;
                }
                if (C) {
                    float2 o2; o2.x = ox; o2.y = oy;
                    *(float2*)(C + (size_t)row * N + col) = o2;
                }
                if (Oh)
                    *(__half2*)(Oh + (size_t)row * N + col) = __floats2half2_rn(ox, oy);
            }
        }
    }
}

// ---------------- tensor-core causal flash attention --------------------------
// 64 queries/block, 128 threads (4 warps), 64-key tiles double-buffered,
// 2 independent CTAs/SM. log2 softmax, mask skip, x4 K / x4t V loads.
#define AT_STAGE 16384
#define AT_SMEM  (8192 + 2*AT_STAGE)    // Q 8KB + 2 x (K 8KB + V 8KB)

__global__ __launch_bounds__(128, 2)
void attn_mma(const __half* __restrict__ QKV, __half* __restrict__ Oh)
{
    extern __shared__ __align__(1024) char smem[];
    const uint32_t sb = smem_u32(smem);
    const int tid = threadIdx.x, wid = tid >> 5, lane = tid & 31;
    const int qt = gridDim.x - 1 - blockIdx.x;
    const int h = blockIdx.y, b = blockIdx.z;
    const int q0 = qt * 64;
    const size_t hoff = (size_t)h * HDIM;
    const float SC = 0.125f * 1.44269504f;

    #pragma unroll
    for (int it = 0; it < 4; it++) {
        int idx = tid + it * 128;
        int r = idx >> 3, c16 = idx & 7;
        uint32_t dst = sb + SWZ128(r * 128 + c16 * 16);
        CP_ASYNC16(dst, QKV + (size_t)(b * TSEQ + q0 + r) * QKVN + hoff + c16 * 8);
    }
    auto load_kv = [&](int s, int kbase) {
        uint32_t base = sb + 8192 + s * AT_STAGE;
        #pragma unroll
        for (int it = 0; it < 8; it++) {
            int idx = tid + it * 128;
            int tl = idx >> 9, r = (idx >> 3) & 63, c16 = idx & 7;
            uint32_t dst = base + tl * 8192 + SWZ128(r * 128 + c16 * 16);
            const __half* src = QKV + (size_t)(b * TSEQ + kbase + r) * QKVN
                                + (tl ? 2048 : 1024) + hoff + c16 * 8;
            CP_ASYNC16(dst, src);
        }
        CP_COMMIT();
    };
    load_kv(0, 0);

    const int a_r  = (lane & 7) + ((lane >> 3) & 1) * 8;
    const int a_cb = (lane >> 4) * 16;
    const int k4_r = (lane & 7) + ((lane >> 4) << 3);
    const int k4_c = ((lane >> 3) & 1) * 16;
    const int v4_r = lane & 15;
    const int v4_c = (lane >> 4) * 16;
    const int rA   = q0 + wid * 16 + (lane >> 2);
    const int wrowmin = q0 + wid * 16;

    float mrow[2] = {-1e30f, -1e30f};
    float lrow[2] = {0.f, 0.f};
    float o[8][4];
    #pragma unroll
    for (int nf = 0; nf < 8; nf++)
        #pragma unroll
        for (int e = 0; e < 4; e++) o[nf][e] = 0.f;
    uint32_t ra[4][4];

    const int nkt = qt + 1;
    for (int kt = 0; kt < nkt; kt++) {
        CP_WAIT(0);
        __syncthreads();
        if (kt + 1 < nkt) load_kv((kt + 1) & 1, (kt + 1) * 64);
        if (kt == 0) {
            #pragma unroll
            for (int ks = 0; ks < 4; ks++) {
                uint32_t off = SWZ128((wid * 16 + a_r) * 128 + ks * 32 + a_cb);
                ldsm_x4(ra[ks], sb + off);
            }
        }
        {
            uint32_t kb = sb + 8192 + (kt & 1) * AT_STAGE;
            float s[8][4];
            #pragma unroll
            for (int nf = 0; nf < 8; nf++)
                #pragma unroll
                for (int e = 0; e < 4; e++) s[nf][e] = 0.f;

            #pragma unroll
            for (int ks = 0; ks < 4; ks++) {
                #pragma unroll
                for (int np = 0; np < 4; np++) {
                    uint32_t koff = SWZ128((np * 16 + k4_r) * 128 + ks * 32 + k4_c);
                    uint32_t kb4[4];
                    ldsm_x4(kb4, kb + koff);
                    mma16816(s[2 * np],     ra[ks], kb4);
                    mma16816(s[2 * np + 1], ra[ks], kb4 + 2);
                }
            }
            if (kt * 64 + 63 > wrowmin) {
                #pragma unroll
                for (int nf = 0; nf < 8; nf++) {
                    int col = kt * 64 + nf * 8 + (lane & 3) * 2;
                    s[nf][0] = (col     > rA)     ? -1e30f : s[nf][0] * SC;
                    s[nf][1] = (col + 1 > rA)     ? -1e30f : s[nf][1] * SC;
                    s[nf][2] = (col     > rA + 8) ? -1e30f : s[nf][2] * SC;
                    s[nf][3] = (col + 1 > rA + 8) ? -1e30f : s[nf][3] * SC;
                }
            } else {
                #pragma unroll
                for (int nf = 0; nf < 8; nf++) {
                    s[nf][0] *= SC; s[nf][1] *= SC;
                    s[nf][2] *= SC; s[nf][3] *= SC;
                }
            }
            float tmA = -1e30f, tmB = -1e30f;
            #pragma unroll
            for (int nf = 0; nf < 8; nf++) {
                tmA = fmaxf(tmA, fmaxf(s[nf][0], s[nf][1]));
                tmB = fmaxf(tmB, fmaxf(s[nf][2], s[nf][3]));
            }
            tmA = fmaxf(tmA, __shfl_xor_sync(0xffffffffu, tmA, 1));
            tmA = fmaxf(tmA, __shfl_xor_sync(0xffffffffu, tmA, 2));
            tmB = fmaxf(tmB, __shfl_xor_sync(0xffffffffu, tmB, 1));
            tmB = fmaxf(tmB, __shfl_xor_sync(0xffffffffu, tmB, 2));
            float mnA = fmaxf(mrow[0], tmA), mnB = fmaxf(mrow[1], tmB);
            float cA = ex2(mrow[0] - mnA), cB = ex2(mrow[1] - mnB);
            uint32_t phi[4][4];
            float lsA = 0.f, lsB = 0.f;
            #pragma unroll
            for (int nf = 0; nf < 8; nf++) {
                float e0 = ex2(s[nf][0] - mnA);
                float e1 = ex2(s[nf][1] - mnA);
                float e2 = ex2(s[nf][2] - mnB);
                float e3 = ex2(s[nf][3] - mnB);
                lsA += e0 + e1;
                lsB += e2 + e3;
                int ks = nf >> 1;
                if (!(nf & 1)) { phi[ks][0] = packh2(e0, e1); phi[ks][1] = packh2(e2, e3); }
                else           { phi[ks][2] = packh2(e0, e1); phi[ks][3] = packh2(e2, e3); }
            }
            lsA += __shfl_xor_sync(0xffffffffu, lsA, 1);
            lsA += __shfl_xor_sync(0xffffffffu, lsA, 2);
            lsB += __shfl_xor_sync(0xffffffffu, lsB, 1);
            lsB += __shfl_xor_sync(0xffffffffu, lsB, 2);
            lrow[0] = lrow[0] * cA + lsA; mrow[0] = mnA;
            lrow[1] = lrow[1] * cB + lsB; mrow[1] = mnB;
            #pragma unroll
            for (int nf = 0; nf < 8; nf++) {
                o[nf][0] *= cA; o[nf][1] *= cA;
                o[nf][2] *= cB; o[nf][3] *= cB;
            }
            #pragma unroll
            for (int ks = 0; ks < 4; ks++) {
                #pragma unroll
                for (int np = 0; np < 4; np++) {
                    uint32_t voff = SWZ128((ks * 16 + v4_r) * 128 + np * 32 + v4_c);
                    uint32_t vb4[4];
                    ldsm_x4t(vb4, kb + 8192 + voff);
                    mma16816(o[2 * np],     phi[ks], vb4);
                    mma16816(o[2 * np + 1], phi[ks], vb4 + 2);
                }
            }
        }
    }

    float iA = 1.f / lrow[0], iB = 1.f / lrow[1];
    #pragma unroll
    for (int nf = 0; nf < 8; nf++) {
        int col = nf * 8 + (lane & 3) * 2;
        size_t baseA = (size_t)(b * TSEQ + rA) * EDIM + hoff + col;
        size_t baseB = (size_t)(b * TSEQ + rA + 8) * EDIM + hoff + col;
        *(__half2*)(Oh + baseA) = __floats2half2_rn(o[nf][0] * iA, o[nf][1] * iA);
        *(__half2*)(Oh + baseB) = __floats2half2_rn(o[nf][2] * iB, o[nf][3] * iB);
    }
}

// ---------------- launch -----------------------------------------------------
extern "C" void kernel_launch(void* const* d_in, const int* in_sizes, int n_in,
                              void* d_out, int out_size)
{
    const float* x    = (const float*)d_in[0];
    const float* ln1g = (const float*)d_in[1];
    const float* ln1b = (const float*)d_in[2];
    const float* Wq   = (const float*)d_in[3];
    const float* Wk   = (const float*)d_in[4];
    const float* Wv   = (const float*)d_in[5];
    const float* Wo   = (const float*)d_in[6];
    const float* bo   = (const float*)d_in[7];
    const float* ln2g = (const float*)d_in[8];
    const float* ln2b = (const float*)d_in[9];
    const float* W1   = (const float*)d_in[10];
    const float* b1   = (const float*)d_in[11];
    const float* W2   = (const float*)d_in[12];
    const float* b2   = (const float*)d_in[13];
    float* out = (float*)d_out;

    float* x1;
    __half *ah, *bh, *qkvh, *wqkv, *woh, *w1h, *w2h;
    cudaGetSymbolAddress((void**)&x1,   g_x1);
    cudaGetSymbolAddress((void**)&ah,   g_ah);
    cudaGetSymbolAddress((void**)&bh,   g_bh);
    cudaGetSymbolAddress((void**)&qkvh, g_qkvh);
    cudaGetSymbolAddress((void**)&wqkv, g_wqkv);
    cudaGetSymbolAddress((void**)&woh,  g_woh);
    cudaGetSymbolAddress((void**)&w1h,  g_w1h);
    cudaGetSymbolAddress((void**)&w2h,  g_w2h);

    cudaFuncSetAttribute(gemm_mma, cudaFuncAttributeMaxDynamicSharedMemorySize, G_SMEM);
    cudaFuncSetAttribute(attn_mma, cudaFuncAttributeMaxDynamicSharedMemorySize, AT_SMEM);

    // weight fp32->fp16 convert (no transpose), one launch
    wconv_all<<<6144, 256>>>(Wq, Wk, Wv, Wo, W1, W2, wqkv, woh, w1h, w2h);

    // 1. LN1 -> fp16
    ln_kernel<<<MTOK/8, 256>>>(x, ln1g, ln1b, ah);

    // 2. fused QKV
    dim3 gQKV(QKVN/128, MTOK/128);
    gemm_mma<<<gQKV, 256, G_SMEM>>>(ah, wqkv, nullptr, qkvh, nullptr, nullptr, 0, QKVN, EDIM);

    // 3. causal MHA -> fp16 (64-query CTAs, 2/SM)
    attn_mma<<<dim3(TSEQ/64, NHEAD, BATCH), 128, AT_SMEM>>>(qkvh, ah);

    // 4. x1 = att @ Wo + bo + x
    dim3 gE(EDIM/128, MTOK/128);
    gemm_mma<<<gE, 256, G_SMEM>>>(ah, woh, x1, nullptr, bo, x, 0, EDIM, EDIM);

    // 5. LN2 -> fp16
    ln_kernel<<<MTOK/8, 256>>>(x1, ln2g, ln2b, ah);

    // 6. hid = relu(h @ W1 + b1)
    dim3 gF(FDIM/128, MTOK/128);
    gemm_mma<<<gF, 256, G_SMEM>>>(ah, w1h, nullptr, bh, b1, nullptr, 1, FDIM, EDIM);

    // 7. out = hid @ W2 + b2 + x1
    gemm_mma<<<gE, 256, G_SMEM>>>(bh, w2h, out, nullptr, b2, x1, 0, EDIM, FDIM);
}

// round 16
// speedup vs baseline: 1.0502x; 1.0502x over previous
#include <cuda_runtime.h>
#include <cuda_fp16.h>
#include <cstdint>
#include <cstddef>

// Problem dims
#define BATCH 2
#define TSEQ  2048
#define EDIM  1024
#define FDIM  4096
#define NHEAD 16
#define HDIM  64
#define MTOK  (BATCH*TSEQ)   // 4096 rows
#define QKVN  (3*EDIM)       // 3072

// ---------------- scratch (device globals: allocation-free) ----------------
__device__ float  g_x1  [MTOK*EDIM];
__device__ __half g_ah  [MTOK*EDIM];     // ln outputs / attention output
__device__ __half g_bh  [MTOK*FDIM];     // mlp hidden
__device__ __half g_qkvh[MTOK*QKVN];     // fused QKV
__device__ __half g_wqkv[QKVN*EDIM];     // [3072 n][1024 k] transposed fp16
__device__ __half g_woh [EDIM*EDIM];     // [N][K] transposed fp16
__device__ __half g_w1h [FDIM*EDIM];
__device__ __half g_w2h [EDIM*FDIM];

// ---------------- PTX helpers (sm_80-compatible only) ----------------
__device__ __forceinline__ uint32_t smem_u32(const void* p) {
    uint32_t a;
    asm("{ .reg .u64 t; cvta.to.shared.u64 t, %1; cvt.u32.u64 %0, t; }" : "=r"(a) : "l"(p));
    return a;
}
#define SWZ128(o) ((o) ^ ((((uint32_t)(o)) >> 3) & 0x70u))

#define CP_ASYNC16(dst, src) \
    asm volatile("cp.async.cg.shared.global [%0], [%1], 16;" :: "r"(dst), "l"(src) : "memory")
#define CP_COMMIT()  asm volatile("cp.async.commit_group;" ::: "memory")
#define CP_WAIT(n)   asm volatile("cp.async.wait_group %0;" :: "n"(n) : "memory")

__device__ __forceinline__ void ldsm_x4(uint32_t* r, uint32_t addr) {
    asm volatile("ldmatrix.sync.aligned.m8n8.x4.shared.b16 {%0,%1,%2,%3}, [%4];"
                 : "=r"(r[0]), "=r"(r[1]), "=r"(r[2]), "=r"(r[3]) : "r"(addr));
}
__device__ __forceinline__ void ldsm_x4t(uint32_t* r, uint32_t addr) {
    asm volatile("ldmatrix.sync.aligned.m8n8.x4.trans.shared.b16 {%0,%1,%2,%3}, [%4];"
                 : "=r"(r[0]), "=r"(r[1]), "=r"(r[2]), "=r"(r[3]) : "r"(addr));
}
__device__ __forceinline__ void mma16816(float* c, const uint32_t* a, const uint32_t* b) {
    asm volatile("mma.sync.aligned.m16n8k16.row.col.f32.f16.f16.f32 "
                 "{%0,%1,%2,%3}, {%4,%5,%6,%7}, {%8,%9}, {%0,%1,%2,%3};"
                 : "+f"(c[0]), "+f"(c[1]), "+f"(c[2]), "+f"(c[3])
                 : "r"(a[0]), "r"(a[1]), "r"(a[2]), "r"(a[3]),
                   "r"(b[0]), "r"(b[1]));
}
__device__ __forceinline__ uint32_t packh2(float a, float b) {
    __half2 t = __floats2half2_rn(a, b);
    return *(uint32_t*)&t;
}
__device__ __forceinline__ float ex2(float x) {
    float r;
    asm("ex2.approx.f32 %0, %1;" : "=f"(r) : "f"(x));
    return r;
}

// ---------------- LayerNorm -> fp16, warp-per-row (no barriers) ---------------
__global__ __launch_bounds__(256)
void ln_kernel(const float* __restrict__ x, const float* __restrict__ g,
               const float* __restrict__ b, __half* __restrict__ yh)
{
    int wid = threadIdx.x >> 5, lane = threadIdx.x & 31;
    int row = blockIdx.x * 8 + wid;
    const float* xr = x + (size_t)row * EDIM;
    float v[32];
    float s = 0.f;
    #pragma unroll
    for (int i = 0; i < 8; i++) {
        float4 t = *(const float4*)(xr + i * 128 + lane * 4);
        v[i*4+0] = t.x; v[i*4+1] = t.y; v[i*4+2] = t.z; v[i*4+3] = t.w;
        s += t.x + t.y + t.z + t.w;
    }
    #pragma unroll
    for (int o = 16; o > 0; o >>= 1) s += __shfl_xor_sync(0xffffffffu, s, o);
    float mean = s * (1.0f / EDIM);
    float s2 = 0.f;
    #pragma unroll
    for (int i = 0; i < 32; i++) { float d = v[i] - mean; s2 += d * d; }
    #pragma unroll
    for (int o = 16; o > 0; o >>= 1) s2 += __shfl_xor_sync(0xffffffffu, s2, o);
    float r = rsqrtf(s2 * (1.0f / EDIM) + 1e-5f);
    __half* yr = yh + (size_t)row * EDIM;
    #pragma unroll
    for (int i = 0; i < 8; i++) {
        int col = i * 128 + lane * 4;
        float4 g4 = *(const float4*)(g + col);
        float4 b4 = *(const float4*)(b + col);
        float o0 = (v[i*4+0] - mean) * r * g4.x + b4.x;
        float o1 = (v[i*4+1] - mean) * r * g4.y + b4.y;
        float o2 = (v[i*4+2] - mean) * r * g4.z + b4.z;
        float o3 = (v[i*4+3] - mean) * r * g4.w + b4.w;
        *(__half2*)(yr + col)     = __floats2half2_rn(o0, o1);
        *(__half2*)(yr + col + 2) = __floats2half2_rn(o2, o3);
    }
}

// ---------------- batched weight transpose, 16B stores -----------------------
// W[K,N] fp32 -> T[N,K] fp16, 64x64 tiles; store phase emits uint4 (8 halves
// of consecutive k per thread) so global stores are 16B and coalesce in 128B runs.
__global__ __launch_bounds__(256)
void wtrans_all(const float* __restrict__ Wq, const float* __restrict__ Wk,
                const float* __restrict__ Wv, const float* __restrict__ Wo,
                const float* __restrict__ W1, const float* __restrict__ W2,
                __half* __restrict__ wqkv, __half* __restrict__ woh,
                __half* __restrict__ w1h, __half* __restrict__ w2h)
{
    __shared__ float tile[64][65];
    int bid = blockIdx.x;
    const float* W; __half* T; int K, N, bx, by;
    if (bid < 1024) {
        int seg = bid >> 8, loc = bid & 255;
        W = (seg == 0) ? Wq : (seg == 1) ? Wk : (seg == 2) ? Wv : Wo;
        T = (seg == 0) ? wqkv : (seg == 1) ? wqkv + EDIM*EDIM
          : (seg == 2) ? wqkv + 2*EDIM*EDIM : woh;
        K = EDIM; N = EDIM;
        bx = (loc & 15) * 64; by = (loc >> 4) * 64;
    } else if (bid < 2048) {
        int loc = bid - 1024;
        W = W1; T = w1h; K = EDIM; N = FDIM;
        bx = (loc & 63) * 64; by = (loc >> 6) * 64;
    } else {
        int loc = bid - 2048;
        W = W2; T = w2h; K = FDIM; N = EDIM;
        bx = (loc & 15) * 64; by = (loc >> 4) * 64;
    }
    int tid = threadIdx.x;
    int lr = tid >> 4;
    int lc = (tid & 15) * 4;
    #pragma unroll
    for (int j = 0; j < 64; j += 16) {
        float4 v = *(const float4*)(W + (size_t)(by + lr + j) * N + bx + lc);
        tile[lr + j][lc]     = v.x;
        tile[lr + j][lc + 1] = v.y;
        tile[lr + j][lc + 2] = v.z;
        tile[lr + j][lc + 3] = v.w;
    }
    __syncthreads();
    int sn = tid >> 3;            // 0..31 (n-row within half-tile)
    int sk = (tid & 7) * 8;       // 8 consecutive k per thread
    #pragma unroll
    for (int jj = 0; jj < 2; jj++) {
        int n = sn + jj * 32;
        __half2 h[4];
        #pragma unroll
        for (int i = 0; i < 4; i++)
            h[i] = __floats2half2_rn(tile[sk + 2*i][n], tile[sk + 2*i + 1][n]);
        uint4 p;
        p.x = *(uint32_t*)&h[0]; p.y = *(uint32_t*)&h[1];
        p.z = *(uint32_t*)&h[2]; p.w = *(uint32_t*)&h[3];
        *(uint4*)(T + (size_t)(bx + n) * K + by + sk) = p;
    }
}

// ---------------- mma.sync fp16 GEMM (1-term, 2 CTAs/SM) ---------------------
// Transposed-B layout (B[N,K]), non-trans x4 B fragments — measured best (R14).
#define G_TILE_B 16384
#define G_STAGE_B (2*G_TILE_B)
#define G_SMEM (3*G_STAGE_B)     // 96 KB

__global__ __launch_bounds__(256, 2)
void gemm_mma(const __half* __restrict__ Ah, const __half* __restrict__ Bh,
              float* __restrict__ C, __half* __restrict__ Oh,
              const float* __restrict__ bias,
              const float* __restrict__ resid, int relu, int N, int K)
{
    extern __shared__ __align__(1024) char smem[];
    const uint32_t sb = smem_u32(smem);
    const int tid  = threadIdx.x;
    const int wid  = tid >> 5, lane = tid & 31;
    const int wm   = wid >> 2;
    const int wn   = wid & 3;
    const int bm = blockIdx.y, bn = blockIdx.x;

    const size_t arow0 = (size_t)bm * 128;
    const size_t brow0 = (size_t)bn * 128;

    auto load_stage = [&](int s, int k0) {
        uint32_t base = sb + s * G_STAGE_B;
        #pragma unroll
        for (int it = 0; it < 8; it++) {
            int c   = tid + it * 256;
            int tl  = c >> 10;
            int idx = c & 1023;
            int r   = idx >> 3;
            int c16 = idx & 7;
            uint32_t dst = base + tl * G_TILE_B + SWZ128(r * 128 + c16 * 16);
            const __half* src = tl
                ? Bh + (brow0 + r) * K + k0 + c16 * 8
                : Ah + (arow0 + r) * K + k0 + c16 * 8;
            CP_ASYNC16(dst, src);
        }
        CP_COMMIT();
    };

    float acc[4][4][4];
    #pragma unroll
    for (int mf = 0; mf < 4; mf++)
        #pragma unroll
        for (int nf = 0; nf < 4; nf++)
            #pragma unroll
            for (int e = 0; e < 4; e++) acc[mf][nf][e] = 0.f;

    const int nch = K >> 6;
    load_stage(0, 0);
    load_stage(1, 64);

    const int a_r  = (lane & 7) + ((lane >> 3) & 1) * 8;
    const int a_cb = (lane >> 4) * 16;
    const int k4_r = (lane & 7) + ((lane >> 4) << 3);
    const int k4_c = ((lane >> 3) & 1) * 16;

    int s3 = 0;
    for (int i = 0; i < nch; i++) {
        if (i + 1 < nch) { CP_WAIT(1); } else { CP_WAIT(0); }
        __syncthreads();
        if (i + 2 < nch) {
            int sn = s3 + 2; if (sn >= 3) sn -= 3;
            load_stage(sn, (i + 2) << 6);
        }

        uint32_t tA = sb + s3 * G_STAGE_B;
        uint32_t tB = tA + G_TILE_B;

        #pragma unroll
        for (int ks = 0; ks < 4; ks++) {
            uint32_t ra[4][4], rb[2][4];
            #pragma unroll
            for (int mf = 0; mf < 4; mf++) {
                uint32_t off = SWZ128((wm * 64 + mf * 16 + a_r) * 128 + ks * 32 + a_cb);
                ldsm_x4(ra[mf], tA + off);
            }
            #pragma unroll
            for (int np = 0; np < 2; np++) {
                uint32_t off = SWZ128((wn * 32 + np * 16 + k4_r) * 128 + ks * 32 + k4_c);
                ldsm_x4(rb[np], tB + off);
            }
            #pragma unroll
            for (int mf = 0; mf < 4; mf++)
                #pragma unroll
                for (int np = 0; np < 2; np++) {
                    mma16816(acc[mf][2 * np],     ra[mf], rb[np]);
                    mma16816(acc[mf][2 * np + 1], ra[mf], rb[np] + 2);
                }
        }
        if (++s3 == 3) s3 = 0;
    }

    int rbase = bm * 128 + wm * 64 + (lane >> 2);
    int cbase = bn * 128 + wn * 32 + (lane & 3) * 2;
    #pragma unroll
    for (int mf = 0; mf < 4; mf++) {
        #pragma unroll
        for (int half = 0; half < 2; half++) {
            int row = rbase + mf * 16 + half * 8;
            #pragma unroll
            for (int nf = 0; nf < 4; nf++) {
                int col = cbase + nf * 8;
                float ox = acc[mf][nf][half * 2 + 0];
                float oy = acc[mf][nf][half * 2 + 1];
                if (bias) {
                    float2 bb = *(const float2*)(bias + col);
                    ox += bb.x; oy += bb.y;
                }
                if (relu) { ox = fmaxf(ox, 0.f); oy = fmaxf(oy, 0.f); }
                if (resid) {
                    float2 rr = *(const float2*)(resid + (size_t)row * N + col);
                    ox += rr.x; oy += rr.y;
                }
                if (C) {
                    float2 o2; o2.x = ox; o2.y = oy;
                    *(float2*)(C + (size_t)row * N + col) = o2;
                }
                if (Oh)
                    *(__half2*)(Oh + (size_t)row * N + col) = __floats2half2_rn(ox, oy);
            }
        }
    }
}

// ---------------- tensor-core causal flash attention --------------------------
// 64 queries/block, 128 threads (4 warps), 64-key tiles double-buffered,
// 2 independent CTAs/SM. log2 softmax, mask skip, x4 K / x4t V loads.
#define AT_STAGE 16384
#define AT_SMEM  (8192 + 2*AT_STAGE)    // Q 8KB + 2 x (K 8KB + V 8KB)

__global__ __launch_bounds__(128, 2)
void attn_mma(const __half* __restrict__ QKV, __half* __restrict__ Oh)
{
    extern __shared__ __align__(1024) char smem[];
    const uint32_t sb = smem_u32(smem);
    const int tid = threadIdx.x, wid = tid >> 5, lane = tid & 31;
    const int qt = gridDim.x - 1 - blockIdx.x;
    const int h = blockIdx.y, b = blockIdx.z;
    const int q0 = qt * 64;
    const size_t hoff = (size_t)h * HDIM;
    const float SC = 0.125f * 1.44269504f;

    #pragma unroll
    for (int it = 0; it < 4; it++) {
        int idx = tid + it * 128;
        int r = idx >> 3, c16 = idx & 7;
        uint32_t dst = sb + SWZ128(r * 128 + c16 * 16);
        CP_ASYNC16(dst, QKV + (size_t)(b * TSEQ + q0 + r) * QKVN + hoff + c16 * 8);
    }
    auto load_kv = [&](int s, int kbase) {
        uint32_t base = sb + 8192 + s * AT_STAGE;
        #pragma unroll
        for (int it = 0; it < 8; it++) {
            int idx = tid + it * 128;
            int tl = idx >> 9, r = (idx >> 3) & 63, c16 = idx & 7;
            uint32_t dst = base + tl * 8192 + SWZ128(r * 128 + c16 * 16);
            const __half* src = QKV + (size_t)(b * TSEQ + kbase + r) * QKVN
                                + (tl ? 2048 : 1024) + hoff + c16 * 8;
            CP_ASYNC16(dst, src);
        }
        CP_COMMIT();
    };
    load_kv(0, 0);

    const int a_r  = (lane & 7) + ((lane >> 3) & 1) * 8;
    const int a_cb = (lane >> 4) * 16;
    const int k4_r = (lane & 7) + ((lane >> 4) << 3);
    const int k4_c = ((lane >> 3) & 1) * 16;
    const int v4_r = lane & 15;
    const int v4_c = (lane >> 4) * 16;
    const int rA   = q0 + wid * 16 + (lane >> 2);
    const int wrowmin = q0 + wid * 16;

    float mrow[2] = {-1e30f, -1e30f};
    float lrow[2] = {0.f, 0.f};
    float o[8][4];
    #pragma unroll
    for (int nf = 0; nf < 8; nf++)
        #pragma unroll
        for (int e = 0; e < 4; e++) o[nf][e] = 0.f;
    uint32_t ra[4][4];

    const int nkt = qt + 1;
    for (int kt = 0; kt < nkt; kt++) {
        CP_WAIT(0);
        __syncthreads();
        if (kt + 1 < nkt) load_kv((kt + 1) & 1, (kt + 1) * 64);
        if (kt == 0) {
            #pragma unroll
            for (int ks = 0; ks < 4; ks++) {
                uint32_t off = SWZ128((wid * 16 + a_r) * 128 + ks * 32 + a_cb);
                ldsm_x4(ra[ks], sb + off);
            }
        }
        {
            uint32_t kb = sb + 8192 + (kt & 1) * AT_STAGE;
            float s[8][4];
            #pragma unroll
            for (int nf = 0; nf < 8; nf++)
                #pragma unroll
                for (int e = 0; e < 4; e++) s[nf][e] = 0.f;

            #pragma unroll
            for (int ks = 0; ks < 4; ks++) {
                #pragma unroll
                for (int np = 0; np < 4; np++) {
                    uint32_t koff = SWZ128((np * 16 + k4_r) * 128 + ks * 32 + k4_c);
                    uint32_t kb4[4];
                    ldsm_x4(kb4, kb + koff);
                    mma16816(s[2 * np],     ra[ks], kb4);
                    mma16816(s[2 * np + 1], ra[ks], kb4 + 2);
                }
            }
            if (kt * 64 + 63 > wrowmin) {
                #pragma unroll
                for (int nf = 0; nf < 8; nf++) {
                    int col = kt * 64 + nf * 8 + (lane & 3) * 2;
                    s[nf][0] = (col     > rA)     ? -1e30f : s[nf][0] * SC;
                    s[nf][1] = (col + 1 > rA)     ? -1e30f : s[nf][1] * SC;
                    s[nf][2] = (col     > rA + 8) ? -1e30f : s[nf][2] * SC;
                    s[nf][3] = (col + 1 > rA + 8) ? -1e30f : s[nf][3] * SC;
                }
            } else {
                #pragma unroll
                for (int nf = 0; nf < 8; nf++) {
                    s[nf][0] *= SC; s[nf][1] *= SC;
                    s[nf][2] *= SC; s[nf][3] *= SC;
                }
            }
            float tmA = -1e30f, tmB = -1e30f;
            #pragma unroll
            for (int nf = 0; nf < 8; nf++) {
                tmA = fmaxf(tmA, fmaxf(s[nf][0], s[nf][1]));
                tmB = fmaxf(tmB, fmaxf(s[nf][2], s[nf][3]));
            }
            tmA = fmaxf(tmA, __shfl_xor_sync(0xffffffffu, tmA, 1));
            tmA = fmaxf(tmA, __shfl_xor_sync(0xffffffffu, tmA, 2));
            tmB = fmaxf(tmB, __shfl_xor_sync(0xffffffffu, tmB, 1));
            tmB = fmaxf(tmB, __shfl_xor_sync(0xffffffffu, tmB, 2));
            float mnA = fmaxf(mrow[0], tmA), mnB = fmaxf(mrow[1], tmB);
            float cA = ex2(mrow[0] - mnA), cB = ex2(mrow[1] - mnB);
            uint32_t phi[4][4];
            float lsA = 0.f, lsB = 0.f;
            #pragma unroll
            for (int nf = 0; nf < 8; nf++) {
                float e0 = ex2(s[nf][0] - mnA);
                float e1 = ex2(s[nf][1] - mnA);
                float e2 = ex2(s[nf][2] - mnB);
                float e3 = ex2(s[nf][3] - mnB);
                lsA += e0 + e1;
                lsB += e2 + e3;
                int ks = nf >> 1;
                if (!(nf & 1)) { phi[ks][0] = packh2(e0, e1); phi[ks][1] = packh2(e2, e3); }
                else           { phi[ks][2] = packh2(e0, e1); phi[ks][3] = packh2(e2, e3); }
            }
            lsA += __shfl_xor_sync(0xffffffffu, lsA, 1);
            lsA += __shfl_xor_sync(0xffffffffu, lsA, 2);
            lsB += __shfl_xor_sync(0xffffffffu, lsB, 1);
            lsB += __shfl_xor_sync(0xffffffffu, lsB, 2);
            lrow[0] = lrow[0] * cA + lsA; mrow[0] = mnA;
            lrow[1] = lrow[1] * cB + lsB; mrow[1] = mnB;
            #pragma unroll
            for (int nf = 0; nf < 8; nf++) {
                o[nf][0] *= cA; o[nf][1] *= cA;
                o[nf][2] *= cB; o[nf][3] *= cB;
            }
            #pragma unroll
            for (int ks = 0; ks < 4; ks++) {
                #pragma unroll
                for (int np = 0; np < 4; np++) {
                    uint32_t voff = SWZ128((ks * 16 + v4_r) * 128 + np * 32 + v4_c);
                    uint32_t vb4[4];
                    ldsm_x4t(vb4, kb + 8192 + voff);
                    mma16816(o[2 * np],     phi[ks], vb4);
                    mma16816(o[2 * np + 1], phi[ks], vb4 + 2);
                }
            }
        }
    }

    float iA = 1.f / lrow[0], iB = 1.f / lrow[1];
    #pragma unroll
    for (int nf = 0; nf < 8; nf++) {
        int col = nf * 8 + (lane & 3) * 2;
        size_t baseA = (size_t)(b * TSEQ + rA) * EDIM + hoff + col;
        size_t baseB = (size_t)(b * TSEQ + rA + 8) * EDIM + hoff + col;
        *(__half2*)(Oh + baseA) = __floats2half2_rn(o[nf][0] * iA, o[nf][1] * iA);
        *(__half2*)(Oh + baseB) = __floats2half2_rn(o[nf][2] * iB, o[nf][3] * iB);
    }
}

// ---------------- launch -----------------------------------------------------
extern "C" void kernel_launch(void* const* d_in, const int* in_sizes, int n_in,
                              void* d_out, int out_size)
{
    const float* x    = (const float*)d_in[0];
    const float* ln1g = (const float*)d_in[1];
    const float* ln1b = (const float*)d_in[2];
    const float* Wq   = (const float*)d_in[3];
    const float* Wk   = (const float*)d_in[4];
    const float* Wv   = (const float*)d_in[5];
    const float* Wo   = (const float*)d_in[6];
    const float* bo   = (const float*)d_in[7];
    const float* ln2g = (const float*)d_in[8];
    const float* ln2b = (const float*)d_in[9];
    const float* W1   = (const float*)d_in[10];
    const float* b1   = (const float*)d_in[11];
    const float* W2   = (const float*)d_in[12];
    const float* b2   = (const float*)d_in[13];
    float* out = (float*)d_out;

    float* x1;
    __half *ah, *bh, *qkvh, *wqkv, *woh, *w1h, *w2h;
    cudaGetSymbolAddress((void**)&x1,   g_x1);
    cudaGetSymbolAddress((void**)&ah,   g_ah);
    cudaGetSymbolAddress((void**)&bh,   g_bh);
    cudaGetSymbolAddress((void**)&qkvh, g_qkvh);
    cudaGetSymbolAddress((void**)&wqkv, g_wqkv);
    cudaGetSymbolAddress((void**)&woh,  g_woh);
    cudaGetSymbolAddress((void**)&w1h,  g_w1h);
    cudaGetSymbolAddress((void**)&w2h,  g_w2h);

    cudaFuncSetAttribute(gemm_mma, cudaFuncAttributeMaxDynamicSharedMemorySize, G_SMEM);
    cudaFuncSetAttribute(attn_mma, cudaFuncAttributeMaxDynamicSharedMemorySize, AT_SMEM);

    // all weight transposes, one launch
    wtrans_all<<<3072, 256>>>(Wq, Wk, Wv, Wo, W1, W2, wqkv, woh, w1h, w2h);

    // 1. LN1 -> fp16
    ln_kernel<<<MTOK/8, 256>>>(x, ln1g, ln1b, ah);

    // 2. fused QKV
    dim3 gQKV(QKVN/128, MTOK/128);
    gemm_mma<<<gQKV, 256, G_SMEM>>>(ah, wqkv, nullptr, qkvh, nullptr, nullptr, 0, QKVN, EDIM);

    // 3. causal MHA -> fp16 (64-query CTAs, 2/SM)
    attn_mma<<<dim3(TSEQ/64, NHEAD, BATCH), 128, AT_SMEM>>>(qkvh, ah);

    // 4. x1 = att @ Wo + bo + x
    dim3 gE(EDIM/128, MTOK/128);
    gemm_mma<<<gE, 256, G_SMEM>>>(ah, woh, x1, nullptr, bo, x, 0, EDIM, EDIM);

    // 5. LN2 -> fp16
    ln_kernel<<<MTOK/8, 256>>>(x1, ln2g, ln2b, ah);

    // 6. hid = relu(h @ W1 + b1)
    dim3 gF(FDIM/128, MTOK/128);
    gemm_mma<<<gF, 256, G_SMEM>>>(ah, w1h, nullptr, bh, b1, nullptr, 1, FDIM, EDIM);

    // 7. out = hid @ W2 + b2 + x1
    gemm_mma<<<gE, 256, G_SMEM>>>(bh, w2h, out, nullptr, b2, x1, 0, EDIM, FDIM);
}

// round 17
// speedup vs baseline: 1.0700x; 1.0188x over previous
#include <cuda_runtime.h>
#include <cuda_fp16.h>
#include <cstdint>
#include <cstddef>

// Problem dims
#define BATCH 2
#define TSEQ  2048
#define EDIM  1024
#define FDIM  4096
#define NHEAD 16
#define HDIM  64
#define MTOK  (BATCH*TSEQ)   // 4096 rows
#define QKVN  (3*EDIM)       // 3072

// ---------------- scratch (device globals: allocation-free) ----------------
__device__ float  g_x1  [MTOK*EDIM];
__device__ __half g_ah  [MTOK*EDIM];     // ln outputs / attention output
__device__ __half g_bh  [MTOK*FDIM];     // mlp hidden
__device__ __half g_qkvh[MTOK*QKVN];     // fused QKV
__device__ __half g_wqkv[QKVN*EDIM];     // [3072 n][1024 k] transposed fp16
__device__ __half g_woh [EDIM*EDIM];     // [N][K] transposed fp16
__device__ __half g_w1h [FDIM*EDIM];
__device__ __half g_w2h [EDIM*FDIM];

// ---------------- PTX helpers (sm_80-compatible only) ----------------
__device__ __forceinline__ uint32_t smem_u32(const void* p) {
    uint32_t a;
    asm("{ .reg .u64 t; cvta.to.shared.u64 t, %1; cvt.u32.u64 %0, t; }" : "=r"(a) : "l"(p));
    return a;
}
#define SWZ128(o) ((o) ^ ((((uint32_t)(o)) >> 3) & 0x70u))

#define CP_ASYNC16(dst, src) \
    asm volatile("cp.async.cg.shared.global [%0], [%1], 16;" :: "r"(dst), "l"(src) : "memory")
#define CP_COMMIT()  asm volatile("cp.async.commit_group;" ::: "memory")
#define CP_WAIT(n)   asm volatile("cp.async.wait_group %0;" :: "n"(n) : "memory")

__device__ __forceinline__ void ldsm_x4(uint32_t* r, uint32_t addr) {
    asm volatile("ldmatrix.sync.aligned.m8n8.x4.shared.b16 {%0,%1,%2,%3}, [%4];"
                 : "=r"(r[0]), "=r"(r[1]), "=r"(r[2]), "=r"(r[3]) : "r"(addr));
}
__device__ __forceinline__ void ldsm_x4t(uint32_t* r, uint32_t addr) {
    asm volatile("ldmatrix.sync.aligned.m8n8.x4.trans.shared.b16 {%0,%1,%2,%3}, [%4];"
                 : "=r"(r[0]), "=r"(r[1]), "=r"(r[2]), "=r"(r[3]) : "r"(addr));
}
__device__ __forceinline__ void mma16816(float* c, const uint32_t* a, const uint32_t* b) {
    asm volatile("mma.sync.aligned.m16n8k16.row.col.f32.f16.f16.f32 "
                 "{%0,%1,%2,%3}, {%4,%5,%6,%7}, {%8,%9}, {%0,%1,%2,%3};"
                 : "+f"(c[0]), "+f"(c[1]), "+f"(c[2]), "+f"(c[3])
                 : "r"(a[0]), "r"(a[1]), "r"(a[2]), "r"(a[3]),
                   "r"(b[0]), "r"(b[1]));
}
__device__ __forceinline__ uint32_t packh2(float a, float b) {
    __half2 t = __floats2half2_rn(a, b);
    return *(uint32_t*)&t;
}
__device__ __forceinline__ float ex2(float x) {
    float r;
    asm("ex2.approx.f32 %0, %1;" : "=f"(r) : "f"(x));
    return r;
}

// ---------------- LayerNorm -> fp16, warp-per-row (no barriers) ---------------
__global__ __launch_bounds__(256)
void ln_kernel(const float* __restrict__ x, const float* __restrict__ g,
               const float* __restrict__ b, __half* __restrict__ yh)
{
    int wid = threadIdx.x >> 5, lane = threadIdx.x & 31;
    int row = blockIdx.x * 8 + wid;
    const float* xr = x + (size_t)row * EDIM;
    float v[32];
    float s = 0.f;
    #pragma unroll
    for (int i = 0; i < 8; i++) {
        float4 t = *(const float4*)(xr + i * 128 + lane * 4);
        v[i*4+0] = t.x; v[i*4+1] = t.y; v[i*4+2] = t.z; v[i*4+3] = t.w;
        s += t.x + t.y + t.z + t.w;
    }
    #pragma unroll
    for (int o = 16; o > 0; o >>= 1) s += __shfl_xor_sync(0xffffffffu, s, o);
    float mean = s * (1.0f / EDIM);
    float s2 = 0.f;
    #pragma unroll
    for (int i = 0; i < 32; i++) { float d = v[i] - mean; s2 += d * d; }
    #pragma unroll
    for (int o = 16; o > 0; o >>= 1) s2 += __shfl_xor_sync(0xffffffffu, s2, o);
    float r = rsqrtf(s2 * (1.0f / EDIM) + 1e-5f);
    __half* yr = yh + (size_t)row * EDIM;
    #pragma unroll
    for (int i = 0; i < 8; i++) {
        int col = i * 128 + lane * 4;
        float4 g4 = *(const float4*)(g + col);
        float4 b4 = *(const float4*)(b + col);
        float o0 = (v[i*4+0] - mean) * r * g4.x + b4.x;
        float o1 = (v[i*4+1] - mean) * r * g4.y + b4.y;
        float o2 = (v[i*4+2] - mean) * r * g4.z + b4.z;
        float o3 = (v[i*4+3] - mean) * r * g4.w + b4.w;
        *(__half2*)(yr + col)     = __floats2half2_rn(o0, o1);
        *(__half2*)(yr + col + 2) = __floats2half2_rn(o2, o3);
    }
}

// ---------------- batched weight transpose, 16B stores -----------------------
__global__ __launch_bounds__(256)
void wtrans_all(const float* __restrict__ Wq, const float* __restrict__ Wk,
                const float* __restrict__ Wv, const float* __restrict__ Wo,
                const float* __restrict__ W1, const float* __restrict__ W2,
                __half* __restrict__ wqkv, __half* __restrict__ woh,
                __half* __restrict__ w1h, __half* __restrict__ w2h)
{
    __shared__ float tile[64][65];
    int bid = blockIdx.x;
    const float* W; __half* T; int K, N, bx, by;
    if (bid < 1024) {
        int seg = bid >> 8, loc = bid & 255;
        W = (seg == 0) ? Wq : (seg == 1) ? Wk : (seg == 2) ? Wv : Wo;
        T = (seg == 0) ? wqkv : (seg == 1) ? wqkv + EDIM*EDIM
          : (seg == 2) ? wqkv + 2*EDIM*EDIM : woh;
        K = EDIM; N = EDIM;
        bx = (loc & 15) * 64; by = (loc >> 4) * 64;
    } else if (bid < 2048) {
        int loc = bid - 1024;
        W = W1; T = w1h; K = EDIM; N = FDIM;
        bx = (loc & 63) * 64; by = (loc >> 6) * 64;
    } else {
        int loc = bid - 2048;
        W = W2; T = w2h; K = FDIM; N = EDIM;
        bx = (loc & 15) * 64; by = (loc >> 4) * 64;
    }
    int tid = threadIdx.x;
    int lr = tid >> 4;
    int lc = (tid & 15) * 4;
    #pragma unroll
    for (int j = 0; j < 64; j += 16) {
        float4 v = *(const float4*)(W + (size_t)(by + lr + j) * N + bx + lc);
        tile[lr + j][lc]     = v.x;
        tile[lr + j][lc + 1] = v.y;
        tile[lr + j][lc + 2] = v.z;
        tile[lr + j][lc + 3] = v.w;
    }
    __syncthreads();
    int sn = tid >> 3;
    int sk = (tid & 7) * 8;
    #pragma unroll
    for (int jj = 0; jj < 2; jj++) {
        int n = sn + jj * 32;
        __half2 h[4];
        #pragma unroll
        for (int i = 0; i < 4; i++)
            h[i] = __floats2half2_rn(tile[sk + 2*i][n], tile[sk + 2*i + 1][n]);
        uint4 p;
        p.x = *(uint32_t*)&h[0]; p.y = *(uint32_t*)&h[1];
        p.z = *(uint32_t*)&h[2]; p.w = *(uint32_t*)&h[3];
        *(uint4*)(T + (size_t)(bx + n) * K + by + sk) = p;
    }
}

// ---------------- mma.sync fp16 GEMM: 128-thread CTA, warp tile 64x64 --------
// 4 warps in 2x2; 2 independent CTAs/SM (22.4K regs/CTA, 96KB smem/CTA).
// Per k16 step: 8 ldsm.x4 feeding 32 MMAs (4:1 density).
#define G_TILE_B 16384
#define G_STAGE_B (2*G_TILE_B)
#define G_SMEM (3*G_STAGE_B)     // 96 KB

__global__ __launch_bounds__(128, 2)
void gemm_mma(const __half* __restrict__ Ah, const __half* __restrict__ Bh,
              float* __restrict__ C, __half* __restrict__ Oh,
              const float* __restrict__ bias,
              const float* __restrict__ resid, int relu, int N, int K)
{
    extern __shared__ __align__(1024) char smem[];
    const uint32_t sb = smem_u32(smem);
    const int tid  = threadIdx.x;
    const int wid  = tid >> 5, lane = tid & 31;
    const int wm   = wid >> 1;          // 0..1 (64 rows)
    const int wn   = wid & 1;           // 0..1 (64 cols)
    const int bm = blockIdx.y, bn = blockIdx.x;

    const size_t arow0 = (size_t)bm * 128;
    const size_t brow0 = (size_t)bn * 128;

    auto load_stage = [&](int s, int k0) {
        uint32_t base = sb + s * G_STAGE_B;
        #pragma unroll
        for (int it = 0; it < 16; it++) {
            int c   = tid + it * 128;
            int tl  = c >> 10;
            int idx = c & 1023;
            int r   = idx >> 3;
            int c16 = idx & 7;
            uint32_t dst = base + tl * G_TILE_B + SWZ128(r * 128 + c16 * 16);
            const __half* src = tl
                ? Bh + (brow0 + r) * K + k0 + c16 * 8
                : Ah + (arow0 + r) * K + k0 + c16 * 8;
            CP_ASYNC16(dst, src);
        }
        CP_COMMIT();
    };

    float acc[4][8][4];
    #pragma unroll
    for (int mf = 0; mf < 4; mf++)
        #pragma unroll
        for (int nf = 0; nf < 8; nf++)
            #pragma unroll
            for (int e = 0; e < 4; e++) acc[mf][nf][e] = 0.f;

    const int nch = K >> 6;
    load_stage(0, 0);
    load_stage(1, 64);

    const int a_r  = (lane & 7) + ((lane >> 3) & 1) * 8;
    const int a_cb = (lane >> 4) * 16;
    const int k4_r = (lane & 7) + ((lane >> 4) << 3);
    const int k4_c = ((lane >> 3) & 1) * 16;

    int s3 = 0;
    for (int i = 0; i < nch; i++) {
        if (i + 1 < nch) { CP_WAIT(1); } else { CP_WAIT(0); }
        __syncthreads();
        if (i + 2 < nch) {
            int sn = s3 + 2; if (sn >= 3) sn -= 3;
            load_stage(sn, (i + 2) << 6);
        }

        uint32_t tA = sb + s3 * G_STAGE_B;
        uint32_t tB = tA + G_TILE_B;

        #pragma unroll
        for (int ks = 0; ks < 4; ks++) {
            uint32_t ra[4][4], rb[4][4];
            #pragma unroll
            for (int mf = 0; mf < 4; mf++) {
                uint32_t off = SWZ128((wm * 64 + mf * 16 + a_r) * 128 + ks * 32 + a_cb);
                ldsm_x4(ra[mf], tA + off);
            }
            #pragma unroll
            for (int np = 0; np < 4; np++) {
                uint32_t off = SWZ128((wn * 64 + np * 16 + k4_r) * 128 + ks * 32 + k4_c);
                ldsm_x4(rb[np], tB + off);
            }
            #pragma unroll
            for (int mf = 0; mf < 4; mf++)
                #pragma unroll
                for (int np = 0; np < 4; np++) {
                    mma16816(acc[mf][2 * np],     ra[mf], rb[np]);
                    mma16816(acc[mf][2 * np + 1], ra[mf], rb[np] + 2);
                }
        }
        if (++s3 == 3) s3 = 0;
    }

    int rbase = bm * 128 + wm * 64 + (lane >> 2);
    int cbase = bn * 128 + wn * 64 + (lane & 3) * 2;
    #pragma unroll
    for (int mf = 0; mf < 4; mf++) {
        #pragma unroll
        for (int half = 0; half < 2; half++) {
            int row = rbase + mf * 16 + half * 8;
            #pragma unroll
            for (int nf = 0; nf < 8; nf++) {
                int col = cbase + nf * 8;
                float ox = acc[mf][nf][half * 2 + 0];
                float oy = acc[mf][nf][half * 2 + 1];
                if (bias) {
                    float2 bb = *(const float2*)(bias + col);
                    ox += bb.x; oy += bb.y;
                }
                if (relu) { ox = fmaxf(ox, 0.f); oy = fmaxf(oy, 0.f); }
                if (resid) {
                    float2 rr = *(const float2*)(resid + (size_t)row * N + col);
                    ox += rr.x; oy += rr.y;
                }
                if (C) {
                    float2 o2; o2.x = ox; o2.y = oy;
                    *(float2*)(C + (size_t)row * N + col) = o2;
                }
                if (Oh)
                    *(__half2*)(Oh + (size_t)row * N + col) = __floats2half2_rn(ox, oy);
            }
        }
    }
}

// ---------------- tensor-core causal flash attention --------------------------
// 64 queries/block, 128 threads (4 warps), 64-key tiles double-buffered,
// 2 independent CTAs/SM. log2 softmax, mask skip, x4 K / x4t V loads.
#define AT_STAGE 16384
#define AT_SMEM  (8192 + 2*AT_STAGE)    // Q 8KB + 2 x (K 8KB + V 8KB)

__global__ __launch_bounds__(128, 2)
void attn_mma(const __half* __restrict__ QKV, __half* __restrict__ Oh)
{
    extern __shared__ __align__(1024) char smem[];
    const uint32_t sb = smem_u32(smem);
    const int tid = threadIdx.x, wid = tid >> 5, lane = tid & 31;
    const int qt = gridDim.x - 1 - blockIdx.x;
    const int h = blockIdx.y, b = blockIdx.z;
    const int q0 = qt * 64;
    const size_t hoff = (size_t)h * HDIM;
    const float SC = 0.125f * 1.44269504f;

    #pragma unroll
    for (int it = 0; it < 4; it++) {
        int idx = tid + it * 128;
        int r = idx >> 3, c16 = idx & 7;
        uint32_t dst = sb + SWZ128(r * 128 + c16 * 16);
        CP_ASYNC16(dst, QKV + (size_t)(b * TSEQ + q0 + r) * QKVN + hoff + c16 * 8);
    }
    auto load_kv = [&](int s, int kbase) {
        uint32_t base = sb + 8192 + s * AT_STAGE;
        #pragma unroll
        for (int it = 0; it < 8; it++) {
            int idx = tid + it * 128;
            int tl = idx >> 9, r = (idx >> 3) & 63, c16 = idx & 7;
            uint32_t dst = base + tl * 8192 + SWZ128(r * 128 + c16 * 16);
            const __half* src = QKV + (size_t)(b * TSEQ + kbase + r) * QKVN
                                + (tl ? 2048 : 1024) + hoff + c16 * 8;
            CP_ASYNC16(dst, src);
        }
        CP_COMMIT();
    };
    load_kv(0, 0);

    const int a_r  = (lane & 7) + ((lane >> 3) & 1) * 8;
    const int a_cb = (lane >> 4) * 16;
    const int k4_r = (lane & 7) + ((lane >> 4) << 3);
    const int k4_c = ((lane >> 3) & 1) * 16;
    const int v4_r = lane & 15;
    const int v4_c = (lane >> 4) * 16;
    const int rA   = q0 + wid * 16 + (lane >> 2);
    const int wrowmin = q0 + wid * 16;

    float mrow[2] = {-1e30f, -1e30f};
    float lrow[2] = {0.f, 0.f};
    float o[8][4];
    #pragma unroll
    for (int nf = 0; nf < 8; nf++)
        #pragma unroll
        for (int e = 0; e < 4; e++) o[nf][e] = 0.f;
    uint32_t ra[4][4];

    const int nkt = qt + 1;
    for (int kt = 0; kt < nkt; kt++) {
        CP_WAIT(0);
        __syncthreads();
        if (kt + 1 < nkt) load_kv((kt + 1) & 1, (kt + 1) * 64);
        if (kt == 0) {
            #pragma unroll
            for (int ks = 0; ks < 4; ks++) {
                uint32_t off = SWZ128((wid * 16 + a_r) * 128 + ks * 32 + a_cb);
                ldsm_x4(ra[ks], sb + off);
            }
        }
        {
            uint32_t kb = sb + 8192 + (kt & 1) * AT_STAGE;
            float s[8][4];
            #pragma unroll
            for (int nf = 0; nf < 8; nf++)
                #pragma unroll
                for (int e = 0; e < 4; e++) s[nf][e] = 0.f;

            #pragma unroll
            for (int ks = 0; ks < 4; ks++) {
                #pragma unroll
                for (int np = 0; np < 4; np++) {
                    uint32_t koff = SWZ128((np * 16 + k4_r) * 128 + ks * 32 + k4_c);
                    uint32_t kb4[4];
                    ldsm_x4(kb4, kb + koff);
                    mma16816(s[2 * np],     ra[ks], kb4);
                    mma16816(s[2 * np + 1], ra[ks], kb4 + 2);
                }
            }
            if (kt * 64 + 63 > wrowmin) {
                #pragma unroll
                for (int nf = 0; nf < 8; nf++) {
                    int col = kt * 64 + nf * 8 + (lane & 3) * 2;
                    s[nf][0] = (col     > rA)     ? -1e30f : s[nf][0] * SC;
                    s[nf][1] = (col + 1 > rA)     ? -1e30f : s[nf][1] * SC;
                    s[nf][2] = (col     > rA + 8) ? -1e30f : s[nf][2] * SC;
                    s[nf][3] = (col + 1 > rA + 8) ? -1e30f : s[nf][3] * SC;
                }
            } else {
                #pragma unroll
                for (int nf = 0; nf < 8; nf++) {
                    s[nf][0] *= SC; s[nf][1] *= SC;
                    s[nf][2] *= SC; s[nf][3] *= SC;
                }
            }
            float tmA = -1e30f, tmB = -1e30f;
            #pragma unroll
            for (int nf = 0; nf < 8; nf++) {
                tmA = fmaxf(tmA, fmaxf(s[nf][0], s[nf][1]));
                tmB = fmaxf(tmB, fmaxf(s[nf][2], s[nf][3]));
            }
            tmA = fmaxf(tmA, __shfl_xor_sync(0xffffffffu, tmA, 1));
            tmA = fmaxf(tmA, __shfl_xor_sync(0xffffffffu, tmA, 2));
            tmB = fmaxf(tmB, __shfl_xor_sync(0xffffffffu, tmB, 1));
            tmB = fmaxf(tmB, __shfl_xor_sync(0xffffffffu, tmB, 2));
            float mnA = fmaxf(mrow[0], tmA), mnB = fmaxf(mrow[1], tmB);
            float cA = ex2(mrow[0] - mnA), cB = ex2(mrow[1] - mnB);
            uint32_t phi[4][4];
            float lsA = 0.f, lsB = 0.f;
            #pragma unroll
            for (int nf = 0; nf < 8; nf++) {
                float e0 = ex2(s[nf][0] - mnA);
                float e1 = ex2(s[nf][1] - mnA);
                float e2 = ex2(s[nf][2] - mnB);
                float e3 = ex2(s[nf][3] - mnB);
                lsA += e0 + e1;
                lsB += e2 + e3;
                int ks = nf >> 1;
                if (!(nf & 1)) { phi[ks][0] = packh2(e0, e1); phi[ks][1] = packh2(e2, e3); }
                else           { phi[ks][2] = packh2(e0, e1); phi[ks][3] = packh2(e2, e3); }
            }
            lsA += __shfl_xor_sync(0xffffffffu, lsA, 1);
            lsA += __shfl_xor_sync(0xffffffffu, lsA, 2);
            lsB += __shfl_xor_sync(0xffffffffu, lsB, 1);
            lsB += __shfl_xor_sync(0xffffffffu, lsB, 2);
            lrow[0] = lrow[0] * cA + lsA; mrow[0] = mnA;
            lrow[1] = lrow[1] * cB + lsB; mrow[1] = mnB;
            #pragma unroll
            for (int nf = 0; nf < 8; nf++) {
                o[nf][0] *= cA; o[nf][1] *= cA;
                o[nf][2] *= cB; o[nf][3] *= cB;
            }
            #pragma unroll
            for (int ks = 0; ks < 4; ks++) {
                #pragma unroll
                for (int np = 0; np < 4; np++) {
                    uint32_t voff = SWZ128((ks * 16 + v4_r) * 128 + np * 32 + v4_c);
                    uint32_t vb4[4];
                    ldsm_x4t(vb4, kb + 8192 + voff);
                    mma16816(o[2 * np],     phi[ks], vb4);
                    mma16816(o[2 * np + 1], phi[ks], vb4 + 2);
                }
            }
        }
    }

    float iA = 1.f / lrow[0], iB = 1.f / lrow[1];
    #pragma unroll
    for (int nf = 0; nf < 8; nf++) {
        int col = nf * 8 + (lane & 3) * 2;
        size_t baseA = (size_t)(b * TSEQ + rA) * EDIM + hoff + col;
        size_t baseB = (size_t)(b * TSEQ + rA + 8) * EDIM + hoff + col;
        *(__half2*)(Oh + baseA) = __floats2half2_rn(o[nf][0] * iA, o[nf][1] * iA);
        *(__half2*)(Oh + baseB) = __floats2half2_rn(o[nf][2] * iB, o[nf][3] * iB);
    }
}

// ---------------- launch -----------------------------------------------------
extern "C" void kernel_launch(void* const* d_in, const int* in_sizes, int n_in,
                              void* d_out, int out_size)
{
    const float* x    = (const float*)d_in[0];
    const float* ln1g = (const float*)d_in[1];
    const float* ln1b = (const float*)d_in[2];
    const float* Wq   = (const float*)d_in[3];
    const float* Wk   = (const float*)d_in[4];
    const float* Wv   = (const float*)d_in[5];
    const float* Wo   = (const float*)d_in[6];
    const float* bo   = (const float*)d_in[7];
    const float* ln2g = (const float*)d_in[8];
    const float* ln2b = (const float*)d_in[9];
    const float* W1   = (const float*)d_in[10];
    const float* b1   = (const float*)d_in[11];
    const float* W2   = (const float*)d_in[12];
    const float* b2   = (const float*)d_in[13];
    float* out = (float*)d_out;

    float* x1;
    __half *ah, *bh, *qkvh, *wqkv, *woh, *w1h, *w2h;
    cudaGetSymbolAddress((void**)&x1,   g_x1);
    cudaGetSymbolAddress((void**)&ah,   g_ah);
    cudaGetSymbolAddress((void**)&bh,   g_bh);
    cudaGetSymbolAddress((void**)&qkvh, g_qkvh);
    cudaGetSymbolAddress((void**)&wqkv, g_wqkv);
    cudaGetSymbolAddress((void**)&woh,  g_woh);
    cudaGetSymbolAddress((void**)&w1h,  g_w1h);
    cudaGetSymbolAddress((void**)&w2h,  g_w2h);

    cudaFuncSetAttribute(gemm_mma, cudaFuncAttributeMaxDynamicSharedMemorySize, G_SMEM);
    cudaFuncSetAttribute(attn_mma, cudaFuncAttributeMaxDynamicSharedMemorySize, AT_SMEM);

    // all weight transposes, one launch
    wtrans_all<<<3072, 256>>>(Wq, Wk, Wv, Wo, W1, W2, wqkv, woh, w1h, w2h);

    // 1. LN1 -> fp16
    ln_kernel<<<MTOK/8, 256>>>(x, ln1g, ln1b, ah);

    // 2. fused QKV
    dim3 gQKV(QKVN/128, MTOK/128);
    gemm_mma<<<gQKV, 128, G_SMEM>>>(ah, wqkv, nullptr, qkvh, nullptr, nullptr, 0, QKVN, EDIM);

    // 3. causal MHA -> fp16 (64-query CTAs, 2/SM)
    attn_mma<<<dim3(TSEQ/64, NHEAD, BATCH), 128, AT_SMEM>>>(qkvh, ah);

    // 4. x1 = att @ Wo + bo + x
    dim3 gE(EDIM/128, MTOK/128);
    gemm_mma<<<gE, 128, G_SMEM>>>(ah, woh, x1, nullptr, bo, x, 0, EDIM, EDIM);

    // 5. LN2 -> fp16
    ln_kernel<<<MTOK/8, 256>>>(x1, ln2g, ln2b, ah);

    // 6. hid = relu(h @ W1 + b1)
    dim3 gF(FDIM/128, MTOK/128);
    gemm_mma<<<gF, 128, G_SMEM>>>(ah, w1h, nullptr, bh, b1, nullptr, 1, FDIM, EDIM);

    // 7. out = hid @ W2 + b2 + x1
    gemm_mma<<<gE, 128, G_SMEM>>>(bh, w2h, out, nullptr, b2, x1, 0, EDIM, FDIM);
}